// round 7
// baseline (speedup 1.0000x reference)
#include <cuda_runtime.h>
#include <cstdint>

// Problem dims
#define B_  256
#define T_  64
#define K_  49
#define H_  512
#define A_  49
#define BT  (B_ * T_)            // 16384
#define BK  (B_ * K_)            // 12544
#define BTH ((size_t)BT * H_)    // 8388608
#define BTK ((size_t)BT * K_)    // 802816
#define CP  52                   // padded row pitch for scratch [*, 52]

// Scratch (device globals; no allocations allowed)
__device__ __align__(16) float g_cv[B_ * K_ * CP];   // content_v  [b,k,52]
__device__ __align__(16) float g_cg[B_ * T_ * CP];   // content_g  [b,t,52]
__device__ __align__(16) float g_cs[B_ * T_ * CP];   // s_t@Ws^T   [b,t,52]
__device__ __align__(16) float g_Wp[3 * 32768];      // permuted W fragments

typedef unsigned long long u64;

__device__ __forceinline__ float tanh_approx(float x) {
    float y;
    asm("tanh.approx.f32 %0, %1;" : "=f"(y) : "f"(x));
    return y;
}
__device__ __forceinline__ u64 pack2(float lo, float hi) {
    u64 d;
    asm("mov.b64 %0, {%1, %2};" : "=l"(d) : "f"(lo), "f"(hi));
    return d;
}
__device__ __forceinline__ uint32_t s2u(const void* p) {
    uint32_t a;
    asm("{ .reg .u64 t; cvta.to.shared.u64 t, %1; cvt.u32.u64 %0, t; }"
        : "=r"(a) : "l"(p));
    return a;
}
__device__ __forceinline__ void cpa16(uint32_t dst, const void* src) {
    asm volatile("cp.async.cg.shared.global [%0], [%1], 16;"
                 :: "r"(dst), "l"(src) : "memory");
}
__device__ __forceinline__ void prefetchL2(const void* p) {
    asm volatile("prefetch.global.L2 [%0];" :: "l"(p));
}
__device__ __forceinline__ float to_tf32(float x) {
    uint32_t y;
    asm("cvt.rna.tf32.f32 %0, %1;" : "=r"(y) : "f"(x));
    return __uint_as_float(y);
}
__device__ __forceinline__ void mma_tf32(float* d,
                                         float a0, float a1, float a2, float a3,
                                         float b0, float b1) {
    asm volatile(
        "mma.sync.aligned.m16n8k8.row.col.f32.tf32.tf32.f32 "
        "{%0,%1,%2,%3}, {%4,%5,%6,%7}, {%8,%9}, {%0,%1,%2,%3};"
        : "+f"(d[0]), "+f"(d[1]), "+f"(d[2]), "+f"(d[3])
        : "r"(__float_as_uint(a0)), "r"(__float_as_uint(a1)),
          "r"(__float_as_uint(a2)), "r"(__float_as_uint(a3)),
          "r"(__float_as_uint(b0)), "r"(__float_as_uint(b1)));
}

// ---------------------------------------------------------------------------
// Permute W matrices into mma.sync B-fragment order.
// ---------------------------------------------------------------------------
__global__ __launch_bounds__(128)
void wperm_kernel(const float* __restrict__ Wv, const float* __restrict__ Wg,
                  const float* __restrict__ Ws_)
{
    int tid = blockIdx.x * 128 + threadIdx.x;       // 0..24575
    int mat = tid / 8192;
    int rem = tid % 8192;
    int S   = rem / 128;
    int j   = (rem / 32) % 4;
    int l   = rem % 32;
    int g = l >> 2, tg = l & 3;
    int k = S * 8 + tg;
    int r0 = 16 * j + g, r1 = r0 + 8;
    const float* W = (mat == 0) ? Wv : (mat == 1) ? Wg : Ws_;
    float4 F;
    F.x = (r0 < A_) ? W[(size_t)r0 * H_ + k]     : 0.f;
    F.y = (r0 < A_) ? W[(size_t)r0 * H_ + k + 4] : 0.f;
    F.z = (r1 < A_) ? W[(size_t)r1 * H_ + k]     : 0.f;
    F.w = (r1 < A_) ? W[(size_t)r1 * H_ + k + 4] : 0.f;
    *(float4*)&g_Wp[(size_t)mat * 32768 + (size_t)rem * 4] = F;
}

// ---------------------------------------------------------------------------
// tf32 mma.sync content GEMM (unchanged).
// ---------------------------------------------------------------------------
__global__ __launch_bounds__(128, 3)
void gemm_mma_kernel(const float* __restrict__ V,   const float* __restrict__ h_t,
                     const float* __restrict__ s_t)
{
    __shared__ __align__(16) float  Xs[64][68];
    __shared__ __align__(16) float4 Bs[1024];       // [s][j][lane]

    const float* X; const float* wp; float* out; int row0;
    const int bid = blockIdx.x;
    if (bid < 196)      { X = V;   wp = g_Wp;          out = g_cv; row0 = bid * 64; }
    else if (bid < 452) { X = h_t; wp = g_Wp + 32768;  out = g_cg; row0 = (bid - 196) * 64; }
    else                { X = s_t; wp = g_Wp + 65536;  out = g_cs; row0 = (bid - 452) * 64; }

    const int tid  = threadIdx.x;
    const int wid  = tid >> 5;
    const int lane = tid & 31;
    const int g    = lane >> 2;
    const int tg   = lane & 3;
    const uint32_t xs_u = s2u(&Xs[0][0]);
    const uint32_t bs_u = s2u(&Bs[0]);

    float acc[8][4];
    #pragma unroll
    for (int n = 0; n < 8; n++)
        #pragma unroll
        for (int c = 0; c < 4; c++) acc[n][c] = 0.f;

    for (int c = 0; c < 8; c++) {
        __syncthreads();
        #pragma unroll
        for (int i = 0; i < 8; i++) {
            int idx = tid + i * 128;
            int r = idx >> 4, c4 = idx & 15;
            cpa16(xs_u + (uint32_t)(r * 68 + c4 * 4) * 4,
                  &X[(size_t)(row0 + r) * H_ + c * 64 + c4 * 4]);
        }
        #pragma unroll
        for (int i = 0; i < 8; i++) {
            int idx = tid + i * 128;
            cpa16(bs_u + (uint32_t)idx * 16, wp + (size_t)c * 4096 + (size_t)idx * 4);
        }
        asm volatile("cp.async.commit_group;" ::: "memory");
        asm volatile("cp.async.wait_group 0;" ::: "memory");
        __syncthreads();

        #pragma unroll
        for (int s = 0; s < 8; s++) {
            float a0 = Xs[16*wid + g    ][s*8 + tg    ];
            float a1 = Xs[16*wid + g + 8][s*8 + tg    ];
            float a2 = Xs[16*wid + g    ][s*8 + tg + 4];
            float a3 = Xs[16*wid + g + 8][s*8 + tg + 4];
            #pragma unroll
            for (int j = 0; j < 4; j++) {
                float4 bf = Bs[(s*4 + j) * 32 + lane];
                mma_tf32(acc[2*j],     a0, a1, a2, a3, bf.x, bf.y);
                mma_tf32(acc[2*j + 1], a0, a1, a2, a3, bf.z, bf.w);
            }
        }
    }

    const int r0g = row0 + 16 * wid + g;
    #pragma unroll
    for (int n = 0; n < 8; n++) {
        int col0 = n * 8 + tg * 2;
        if (col0 < CP) {
            *(u64*)&out[(size_t)r0g * CP + col0]       = pack2(acc[n][0], acc[n][1]);
            *(u64*)&out[(size_t)(r0g + 8) * CP + col0] = pack2(acc[n][2], acc[n][3]);
        }
    }
}

// ---------------------------------------------------------------------------
// zsoft: z_t + z_ext + softmax(alpha) + extended softmax(beta). (unchanged)
// ---------------------------------------------------------------------------
#define TZ 32
#define ZP 53

__global__ __launch_bounds__(256)
void zsoft_kernel(const float* __restrict__ Wh,
                  float* __restrict__ out_alpha, float* __restrict__ out_beta)
{
    const int b  = blockIdx.y;
    const int t0 = blockIdx.x * TZ;
    __shared__ float cvs[K_ * ZP];
    __shared__ float cgs[TZ * ZP];
    __shared__ float css[TZ * ZP];
    __shared__ float whs[A_];
    __shared__ float zes[TZ];
    __shared__ float zs[TZ * 50];
    const int tid = threadIdx.x;

    for (int i = tid; i < K_ * A_; i += 256) {
        int k = i / A_, a = i % A_;
        cvs[k * ZP + a] = g_cv[((size_t)b * K_ + k) * CP + a];
    }
    for (int i = tid; i < TZ * A_; i += 256) {
        int t = i / A_, a = i % A_;
        size_t src = ((size_t)b * T_ + t0 + t) * CP + a;
        cgs[t * ZP + a] = g_cg[src];
        css[t * ZP + a] = g_cs[src];
    }
    if (tid < A_) whs[tid] = Wh[tid];
    __syncthreads();

    for (int item = tid; item < TZ * K_ + TZ; item += 256) {
        const float* rowA;
        const float* rowB;
        if (item < TZ * K_) {
            int t = item / K_, k = item % K_;
            rowA = &cgs[t * ZP];
            rowB = &cvs[k * ZP];
        } else {
            int t = item - TZ * K_;
            rowA = &cgs[t * ZP];
            rowB = &css[t * ZP];
        }
        float s0 = 0.f, s1 = 0.f;
        #pragma unroll
        for (int a = 0; a < 48; a += 2) {
            s0 = fmaf(tanh_approx(rowA[a]   + rowB[a]),   whs[a],   s0);
            s1 = fmaf(tanh_approx(rowA[a+1] + rowB[a+1]), whs[a+1], s1);
        }
        s0 = fmaf(tanh_approx(rowA[48] + rowB[48]), whs[48], s0);
        float z = s0 + s1;
        if (item < TZ * K_) {
            int t = item / K_, k = item % K_;
            zs[t * 50 + k] = z;
        } else {
            zes[item - TZ * K_] = z;
        }
    }
    __syncthreads();

    const int warp = tid >> 5, lane = tid & 31;
    for (int t = warp; t < TZ; t += 8) {
        float z1 = (lane < K_)      ? zs[t*50 + lane]      : -1e30f;
        float z2 = (lane + 32 < K_) ? zs[t*50 + lane + 32] : -1e30f;
        float m = fmaxf(z1, z2);
        #pragma unroll
        for (int o = 16; o; o >>= 1) m = fmaxf(m, __shfl_xor_sync(0xffffffffu, m, o));
        float e1 = (lane < K_)      ? __expf(z1 - m) : 0.f;
        float e2 = (lane + 32 < K_) ? __expf(z2 - m) : 0.f;
        float s = e1 + e2;
        #pragma unroll
        for (int o = 16; o; o >>= 1) s += __shfl_xor_sync(0xffffffffu, s, o);
        float inv = 1.f / s;
        size_t bt = (size_t)b * T_ + t0 + t;
        if (lane < K_)      out_alpha[bt * K_ + lane]      = e1 * inv;
        if (lane + 32 < K_) out_alpha[bt * K_ + lane + 32] = e2 * inv;
        if (lane == 0) {
            float ze = zes[t];
            float m2 = fmaxf(m, ze);
            float ee = __expf(ze - m2);
            float denom = s * __expf(m - m2) + ee;
            out_beta[bt] = ee / denom;
        }
    }
}

// ---------------------------------------------------------------------------
// chat via 3xTF32 mma (fp32-grade precision): c_hat = beta*s_t + (1-beta)*(alpha@V).
// Block (hc 128-wide, b); 256 thr = 8 warps = 4 m16-tiles x 2 n64-halves.
// Operand hi/lo split happens in registers at fragment load; 3 MMAs per tile:
// hi*hi + lo*hi + hi*lo (lo*lo dropped). V tile via cp.async; s_t L2-prefetch.
// ---------------------------------------------------------------------------
#define VP 136
#define AP 57

__global__ __launch_bounds__(256)
void chat_mma_kernel(const float* __restrict__ V, const float* __restrict__ s_t,
                     const float* __restrict__ alpha, const float* __restrict__ beta,
                     float* __restrict__ out)
{
    const int b  = blockIdx.y;
    const int hc = blockIdx.x * 128;
    __shared__ __align__(16) float Vs[56][VP];   // rows 49..55 zero
    __shared__ float as[T_][AP];                 // cols 49..55 zero
    __shared__ float bs[T_];
    const int tid = threadIdx.x;
    const uint32_t vs_u = s2u(&Vs[0][0]);

    // Prefetch the epilogue's s_t working set into L2 (one 128B line/thread).
    {
        int t = tid >> 2, ln = tid & 3;
        prefetchL2(&s_t[((size_t)b * T_ + t) * H_ + hc + ln * 32]);
    }

    // V tile via cp.async (rows < 49); zero-fill pad rows 49..55.
    for (int idx = tid; idx < K_ * 32; idx += 256) {
        int k = idx >> 5, c = idx & 31;
        cpa16(vs_u + (uint32_t)(k * VP + c * 4) * 4,
              &V[((size_t)b * K_ + k) * H_ + hc + c * 4]);
    }
    for (int idx = tid; idx < 7 * 34; idx += 256) {
        int k = 49 + idx / 34, c = idx % 34;
        *(float4*)&Vs[k][c * 4] = make_float4(0.f, 0.f, 0.f, 0.f);
    }
    asm volatile("cp.async.commit_group;" ::: "memory");
    // alpha tile (cols >= 49 zero) — overlaps with cp.async in flight
    for (int i = tid; i < T_ * 56; i += 256) {
        int t = i / 56, k = i % 56;
        as[t][k] = (k < K_) ? alpha[((size_t)b * T_ + t) * K_ + k] : 0.f;
    }
    if (tid < T_) bs[tid] = beta[(size_t)b * T_ + tid];
    asm volatile("cp.async.wait_group 0;" ::: "memory");
    __syncthreads();

    const int wid  = tid >> 5;
    const int lane = tid & 31;
    const int g    = lane >> 2;
    const int tg   = lane & 3;
    const int mw   = wid & 3;      // m16 tile (t-range 16mw..16mw+15)
    const int nh   = wid >> 2;     // n 64-half

    float acc[8][4];
    #pragma unroll
    for (int j = 0; j < 8; j++)
        #pragma unroll
        for (int c = 0; c < 4; c++) acc[j][c] = 0.f;

    #pragma unroll
    for (int ks = 0; ks < 7; ks++) {
        float a0 = as[16*mw + g    ][ks*8 + tg    ];
        float a1 = as[16*mw + g + 8][ks*8 + tg    ];
        float a2 = as[16*mw + g    ][ks*8 + tg + 4];
        float a3 = as[16*mw + g + 8][ks*8 + tg + 4];
        float ah0 = to_tf32(a0), al0 = a0 - ah0;
        float ah1 = to_tf32(a1), al1 = a1 - ah1;
        float ah2 = to_tf32(a2), al2 = a2 - ah2;
        float ah3 = to_tf32(a3), al3 = a3 - ah3;
        #pragma unroll
        for (int j = 0; j < 8; j++) {
            int n = nh*64 + j*8 + g;
            float b0 = Vs[ks*8 + tg    ][n];
            float b1 = Vs[ks*8 + tg + 4][n];
            float bh0 = to_tf32(b0), bl0 = b0 - bh0;
            float bh1 = to_tf32(b1), bl1 = b1 - bh1;
            mma_tf32(acc[j], al0, al1, al2, al3, bh0, bh1);   // lo*hi
            mma_tf32(acc[j], ah0, ah1, ah2, ah3, bl0, bl1);   // hi*lo
            mma_tf32(acc[j], ah0, ah1, ah2, ah3, bh0, bh1);   // hi*hi
        }
    }

    // Blend epilogue: D frag (g,2tg),(g,2tg+1),(g+8,2tg),(g+8,2tg+1)
    const int t0 = 16*mw + g;
    const float bv0 = bs[t0],     ob0 = 1.f - bv0;
    const float bv1 = bs[t0 + 8], ob1 = 1.f - bv1;
    #pragma unroll
    for (int j = 0; j < 8; j++) {
        int col = hc + nh*64 + j*8 + 2*tg;
        size_t base0 = ((size_t)b * T_ + t0)     * H_ + col;
        size_t base1 = ((size_t)b * T_ + t0 + 8) * H_ + col;
        float2 s0 = *(const float2*)&s_t[base0];
        float2 s1 = *(const float2*)&s_t[base1];
        float2 o0, o1;
        o0.x = fmaf(bv0, s0.x, ob0 * acc[j][0]);
        o0.y = fmaf(bv0, s0.y, ob0 * acc[j][1]);
        o1.x = fmaf(bv1, s1.x, ob1 * acc[j][2]);
        o1.y = fmaf(bv1, s1.y, ob1 * acc[j][3]);
        *(float2*)&out[base0] = o0;
        *(float2*)&out[base1] = o1;
    }
}

extern "C" void kernel_launch(void* const* d_in, const int* in_sizes, int n_in,
                              void* d_out, int out_size)
{
    (void)in_sizes; (void)n_in; (void)out_size;
    const float* V   = (const float*)d_in[0];   // (B,K,H)
    const float* h_t = (const float*)d_in[1];   // (B,T,H)
    const float* s_t = (const float*)d_in[2];   // (B,T,H)
    const float* Wv  = (const float*)d_in[3];   // (K,H)
    const float* Wg  = (const float*)d_in[4];   // (K,H)
    const float* Ws_ = (const float*)d_in[5];   // (K,H)
    const float* Wh  = (const float*)d_in[6];   // (1,K)

    float* out       = (float*)d_out;
    float* out_chat  = out;                 // (B,T,H)
    float* out_alpha = out + BTH;           // (B,T,K)
    float* out_beta  = out + BTH + BTK;     // (B,T,1)

    wperm_kernel<<<192, 128>>>(Wv, Wg, Ws_);
    gemm_mma_kernel<<<708, 128>>>(V, h_t, s_t);
    zsoft_kernel<<<dim3(2, B_), 256>>>(Wh, out_alpha, out_beta);
    chat_mma_kernel<<<dim3(4, B_), 256>>>(V, s_t, out_alpha, out_beta, out_chat);
}